// round 2
// baseline (speedup 1.0000x reference)
#include <cuda_runtime.h>
#include <math.h>

// ---------------- problem constants ----------------
#define BB   1024
#define IN_  512
#define HH   600
#define NU_  6
#define KK_  4
#define QK_  64
#define VD_  400
#define NCH_ 4
#define CQ_  32
#define CK_  32
#define CV_  100
#define G4H  (4*HH)          // 2400
#define TOT  ((long)BB*NU_*HH)

// ---------------- scratch (device globals, no allocation) ----------------
__device__ float g_k0[BB*QK_];
__device__ float g_v0[BB*VD_];
__device__ float g_ql[NU_*BB*QK_];
__device__ float g_inputs[NU_*BB*VD_];
__device__ float g_mask[BB*NU_];
__device__ float g_gates[(long)NU_*BB*G4H];
__device__ float g_cnew[NU_*BB*HH];
__device__ float g_hrnn[NU_*BB*HH];
__device__ float g_qc[NU_*BB*NCH_*CQ_];
__device__ float g_kc[NU_*BB*NCH_*CK_];
__device__ float g_vc[NU_*BB*NCH_*CV_];
__device__ float g_ctx[NU_*BB*NCH_*CV_];
__device__ float g_ctx2[NU_*BB*HH];

// ---------------- tiled SGEMM ----------------
// C[M,N] (+)= A[M,K] * B   (B is KxN row-major if !TRANSB, NxK row-major if TRANSB)
// per-z-slice strides for batched-over-unit GEMMs.
#define BM 64
#define BN 64
#define BKt 8
#define TM 4
#define TN 4

template<bool TRANSB, bool ACCUM, bool BIAS>
__global__ void gemm_k(const float* __restrict__ A, int lda, long sA,
                       const float* __restrict__ Bw, long sB,
                       const float* __restrict__ bias,
                       float* __restrict__ C, int ldc, long sC,
                       int M, int N, int Kd)
{
    int u = blockIdx.z;
    A  += (long)u * sA;
    Bw += (long)u * sB;
    C  += (long)u * sC;

    __shared__ float As[BKt][BM];
    __shared__ float Bs[BKt][BN];

    int tid = threadIdx.x;       // 256 threads
    int tr  = tid >> 4;          // 0..15
    int tc  = tid & 15;          // 0..15
    int rowBase = blockIdx.y * BM;
    int colBase = blockIdx.x * BN;

    float acc[TM][TN] = {};

    for (int k0 = 0; k0 < Kd; k0 += BKt) {
        // load A tile: 64x8 = 512 elems
        #pragma unroll
        for (int i = 0; i < 2; i++) {
            int e = tid + i*256;
            int m = e >> 3, kk = e & 7;
            int gm = rowBase + m;
            As[kk][m] = (gm < M) ? A[(long)gm*lda + k0 + kk] : 0.f;
        }
        // load B tile
        #pragma unroll
        for (int i = 0; i < 2; i++) {
            int e = tid + i*256;
            if (!TRANSB) {
                int kk = e >> 6, n = e & 63;
                int gn = colBase + n;
                Bs[kk][n] = (gn < N) ? Bw[(long)(k0+kk)*N + gn] : 0.f;
            } else {
                int n = e >> 3, kk = e & 7;
                int gn = colBase + n;
                Bs[kk][n] = (gn < N) ? Bw[(long)gn*Kd + k0 + kk] : 0.f;
            }
        }
        __syncthreads();
        #pragma unroll
        for (int kk = 0; kk < BKt; kk++) {
            float a[TM], b[TN];
            #pragma unroll
            for (int i = 0; i < TM; i++) a[i] = As[kk][tr*TM+i];
            #pragma unroll
            for (int j = 0; j < TN; j++) b[j] = Bs[kk][tc*TN+j];
            #pragma unroll
            for (int i = 0; i < TM; i++)
                #pragma unroll
                for (int j = 0; j < TN; j++)
                    acc[i][j] = fmaf(a[i], b[j], acc[i][j]);
        }
        __syncthreads();
    }

    #pragma unroll
    for (int i = 0; i < TM; i++) {
        int gm = rowBase + tr*TM + i;
        if (gm >= M) continue;
        #pragma unroll
        for (int j = 0; j < TN; j++) {
            int gn = colBase + tc*TN + j;
            if (gn >= N) continue;
            float v = acc[i][j];
            if (BIAS)  v += bias[gn];
            long ci = (long)gm*ldc + gn;
            if (ACCUM) C[ci] += v; else C[ci] = v;
        }
    }
}

// ---------------- scores / topk / softmax / inputs ----------------
__global__ void scores_kernel(const float* __restrict__ bk,   // [QK]
                              const float* __restrict__ bv)   // [VD]
{
    int b = blockIdx.x;
    int tid = threadIdx.x;   // 256
    __shared__ float s_sc[NU_][2];
    __shared__ float s_p[NU_][2];
    __shared__ float s_m[NU_];

    if (tid < NU_*2) {
        int u = tid >> 1, t = tid & 1;
        const float* q  = g_ql + ((long)u*BB + b)*QK_;
        const float* kv = (t == 0) ? (g_k0 + (long)b*QK_) : bk;
        float s = 0.f;
        #pragma unroll 8
        for (int i = 0; i < QK_; i++) s += q[i]*kv[i];
        s_sc[u][t] = s * 0.125f;   // 1/sqrt(64)
    }
    __syncthreads();
    if (tid == 0) {
        for (int u = 0; u < NU_; u++) {
            int cnt = 0;
            float cu = s_sc[u][0];
            for (int v = 0; v < NU_; v++) {
                float av = s_sc[v][0];
                if (av > cu || (av == cu && v < u)) cnt++;
            }
            float m = (cnt < KK_) ? 1.f : 0.f;
            s_m[u] = m;
            g_mask[(long)b*NU_ + u] = m;
        }
    }
    if (tid < NU_) {
        int u = tid;
        float s0 = s_sc[u][0], s1 = s_sc[u][1];
        float mx = fmaxf(s0, s1);
        float e0 = expf(s0-mx), e1 = expf(s1-mx);
        float inv = 1.f/(e0+e1);
        s_p[u][0] = e0*inv; s_p[u][1] = e1*inv;
    }
    __syncthreads();
    for (int v = tid; v < VD_; v += blockDim.x) {
        float v0v = g_v0[(long)b*VD_ + v];
        float bvv = bv[v];
        #pragma unroll
        for (int u = 0; u < NU_; u++) {
            g_inputs[((long)u*BB + b)*VD_ + v] = s_m[u]*(s_p[u][0]*v0v + s_p[u][1]*bvv);
        }
    }
}

// ---------------- LSTM elementwise ----------------
__global__ void lstm_kernel(const float* __restrict__ bih,    // [NU][4H]
                            const float* __restrict__ bhh,    // [NU][4H]
                            const float* __restrict__ cs)     // [B][NU][H]
{
    long idx = (long)blockIdx.x*blockDim.x + threadIdx.x;
    if (idx >= (long)NU_*BB*HH) return;
    int h  = idx % HH;
    long bu = idx / HH;
    int b  = bu % BB;
    int u  = bu / BB;
    const float* g  = g_gates + ((long)u*BB + b)*G4H;
    const float* bi = bih + (long)u*G4H;
    const float* bh = bhh + (long)u*G4H;
    float ig = g[h]        + bi[h]        + bh[h];
    float fg = g[HH+h]     + bi[HH+h]     + bh[HH+h];
    float gg = g[2*HH+h]   + bi[2*HH+h]   + bh[2*HH+h];
    float og = g[3*HH+h]   + bi[3*HH+h]   + bh[3*HH+h];
    float si = 1.f/(1.f+expf(-ig));
    float sf = 1.f/(1.f+expf(-fg));
    float so = 1.f/(1.f+expf(-og));
    float tg = tanhf(gg);
    float c  = cs[((long)b*NU_ + u)*HH + h];
    float cn = sf*c + si*tg;
    g_cnew[idx] = cn;
    g_hrnn[idx] = so*tanhf(cn);
}

// ---------------- per-batch mini attention ----------------
__global__ void attn_kernel()
{
    int b = blockIdx.x;
    int tid = threadIdx.x;   // 256
    __shared__ float s_q[NU_][NCH_*CQ_];
    __shared__ float s_k[NU_][NCH_*CK_];
    __shared__ float s_v[NU_][NCH_*CV_];
    __shared__ float s_att[NCH_][NU_][NU_];
    __shared__ float s_m[NU_];

    if (tid < NU_) s_m[tid] = g_mask[(long)b*NU_ + tid];
    for (int i = tid; i < NU_*NCH_*CQ_; i += 256) {
        int u = i / (NCH_*CQ_), o = i % (NCH_*CQ_);
        s_q[u][o] = g_qc[((long)u*BB + b)*(NCH_*CQ_) + o];
        s_k[u][o] = g_kc[((long)u*BB + b)*(NCH_*CK_) + o];
    }
    for (int i = tid; i < NU_*NCH_*CV_; i += 256) {
        int u = i / (NCH_*CV_), o = i % (NCH_*CV_);
        s_v[u][o] = g_vc[((long)u*BB + b)*(NCH_*CV_) + o];
    }
    __syncthreads();
    if (tid < NCH_*NU_*NU_) {
        int ch = tid / (NU_*NU_);
        int r  = tid % (NU_*NU_);
        int u = r / NU_, t = r % NU_;
        float s = 0.f;
        #pragma unroll
        for (int q = 0; q < CQ_; q++) s += s_q[u][ch*CQ_+q]*s_k[t][ch*CK_+q];
        s_att[ch][u][t] = s * 0.17677669529663688f;  // 1/sqrt(32)
    }
    __syncthreads();
    if (tid < NCH_*NU_) {
        int ch = tid / NU_, u = tid % NU_;
        float mx = -1e30f;
        #pragma unroll
        for (int t = 0; t < NU_; t++) mx = fmaxf(mx, s_att[ch][u][t]);
        float e[NU_]; float sum = 0.f;
        #pragma unroll
        for (int t = 0; t < NU_; t++) { e[t] = expf(s_att[ch][u][t]-mx); sum += e[t]; }
        float inv = s_m[u]/sum;
        #pragma unroll
        for (int t = 0; t < NU_; t++) s_att[ch][u][t] = e[t]*inv;
    }
    __syncthreads();
    for (int i = tid; i < NU_*NCH_*CV_; i += 256) {
        int u = i / (NCH_*CV_), o = i % (NCH_*CV_);
        int ch = o / CV_, cv = o % CV_;
        float s = 0.f;
        #pragma unroll
        for (int t = 0; t < NU_; t++) s += s_att[ch][u][t]*s_v[t][ch*CV_+cv];
        g_ctx[((long)u*BB + b)*(NCH_*CV_) + o] = s;
    }
}

// ---------------- residual + LayerNorm + blend ----------------
__global__ void final_kernel(const float* __restrict__ hs,    // [B][NU][H]
                             const float* __restrict__ cs,    // [B][NU][H]
                             const float* __restrict__ ln_g,
                             const float* __restrict__ ln_b,
                             float* __restrict__ out)
{
    int blk = blockIdx.x;           // u*B + b
    int u = blk / BB, b = blk % BB;
    int tid = threadIdx.x;          // 256
    int lane = tid & 31, wid = tid >> 5;
    __shared__ float sv[HH];
    __shared__ float wsum[8], wsq[8];

    const float* c2 = g_ctx2 + (long)blk*HH;
    const float* hr = g_hrnn + (long)blk*HH;
    float lsum = 0.f, lsq = 0.f;
    for (int h = tid; h < HH; h += 256) {
        float v = c2[h] + hr[h];
        sv[h] = v; lsum += v; lsq += v*v;
    }
    #pragma unroll
    for (int o = 16; o > 0; o >>= 1) {
        lsum += __shfl_down_sync(0xffffffffu, lsum, o);
        lsq  += __shfl_down_sync(0xffffffffu, lsq, o);
    }
    if (lane == 0) { wsum[wid] = lsum; wsq[wid] = lsq; }
    __syncthreads();
    if (tid == 0) {
        float s = 0.f, q = 0.f;
        #pragma unroll
        for (int w = 0; w < 8; w++) { s += wsum[w]; q += wsq[w]; }
        wsum[0] = s; wsq[0] = q;
    }
    __syncthreads();
    float mu  = wsum[0] * (1.f/HH);
    float var = wsq[0] * (1.f/HH) - mu*mu;
    float inv = rsqrtf(var + 1e-5f);
    float m   = g_mask[(long)b*NU_ + u];
    const float* cn = g_cnew + (long)blk*HH;
    for (int h = tid; h < HH; h += 256) {
        float hn = (sv[h]-mu)*inv*ln_g[h] + ln_b[h];
        long oi = ((long)b*NU_ + u)*HH + h;
        out[oi]       = m*hn    + (1.f-m)*hs[oi];
        out[TOT + oi] = m*cn[h] + (1.f-m)*cs[oi];
    }
}

// ---------------- launch ----------------
static inline dim3 gg(int N, int M, int Z) { return dim3((N+BN-1)/BN, (M+BM-1)/BM, Z); }

extern "C" void kernel_launch(void* const* d_in, const int* in_sizes, int n_in,
                              void* d_out, int out_size)
{
    const float* x    = (const float*)d_in[0];
    const float* hs   = (const float*)d_in[1];
    const float* cs   = (const float*)d_in[2];
    const float* Wk   = (const float*)d_in[3];
    const float* bk   = (const float*)d_in[4];
    const float* Wv   = (const float*)d_in[5];
    const float* bv   = (const float*)d_in[6];
    const float* Wq   = (const float*)d_in[7];
    const float* Wqc  = (const float*)d_in[8];
    const float* Wkc  = (const float*)d_in[9];
    const float* Wvc  = (const float*)d_in[10];
    const float* Woc  = (const float*)d_in[11];
    const float* Wih  = (const float*)d_in[12];
    const float* Whh  = (const float*)d_in[13];
    const float* bih  = (const float*)d_in[14];
    const float* bhh  = (const float*)d_in[15];
    const float* ln_g = (const float*)d_in[16];
    const float* ln_b = (const float*)d_in[17];
    float* out = (float*)d_out;

    float *k0, *v0, *ql, *inp, *gates, *hrnn, *qc, *kc, *vc, *ctx, *ctx2;
    cudaGetSymbolAddress((void**)&k0,   g_k0);
    cudaGetSymbolAddress((void**)&v0,   g_v0);
    cudaGetSymbolAddress((void**)&ql,   g_ql);
    cudaGetSymbolAddress((void**)&inp,  g_inputs);
    cudaGetSymbolAddress((void**)&gates,g_gates);
    cudaGetSymbolAddress((void**)&hrnn, g_hrnn);
    cudaGetSymbolAddress((void**)&qc,   g_qc);
    cudaGetSymbolAddress((void**)&kc,   g_kc);
    cudaGetSymbolAddress((void**)&vc,   g_vc);
    cudaGetSymbolAddress((void**)&ctx,  g_ctx);
    cudaGetSymbolAddress((void**)&ctx2, g_ctx2);

    // 1) k0 = x @ Wk + bk    (M=B, N=64, K=512)
    gemm_k<false,false,true><<<gg(QK_, BB, 1), 256>>>(x, IN_, 0, Wk, 0, bk, k0, QK_, 0, BB, QK_, IN_);
    // 2) v0 = x @ Wv + bv    (N=400)
    gemm_k<false,false,true><<<gg(VD_, BB, 1), 256>>>(x, IN_, 0, Wv, 0, bv, v0, VD_, 0, BB, VD_, IN_);
    // 3) ql[u] = hs_u @ Wq[u]   (N=64, K=600), batched over u
    gemm_k<false,false,false><<<gg(QK_, BB, NU_), 256>>>(hs, NU_*HH, HH, Wq, (long)HH*QK_, nullptr,
                                                         ql, QK_, (long)BB*QK_, BB, QK_, HH);
    // 4) scores / topk / softmax / inputs
    scores_kernel<<<BB, 256>>>(bk, bv);
    // 5) gates = inputs[u] @ Wih[u]^T   (N=2400, K=400)
    gemm_k<true,false,false><<<gg(G4H, BB, NU_), 256>>>(inp, VD_, (long)BB*VD_, Wih, (long)G4H*VD_, nullptr,
                                                        gates, G4H, (long)BB*G4H, BB, G4H, VD_);
    // 6) gates += hs_u @ Whh[u]^T       (K=600)
    gemm_k<true,true,false><<<gg(G4H, BB, NU_), 256>>>(hs, NU_*HH, HH, Whh, (long)G4H*HH, nullptr,
                                                       gates, G4H, (long)BB*G4H, BB, G4H, HH);
    // 7) LSTM
    {
        long tot = (long)NU_*BB*HH;
        lstm_kernel<<<(int)((tot+255)/256), 256>>>(bih, bhh, cs);
    }
    // 8..10) qc/kc/vc projections from h_rnn
    gemm_k<false,false,false><<<gg(NCH_*CQ_, BB, NU_), 256>>>(hrnn, HH, (long)BB*HH, Wqc, (long)HH*NCH_*CQ_, nullptr,
                                                              qc, NCH_*CQ_, (long)BB*NCH_*CQ_, BB, NCH_*CQ_, HH);
    gemm_k<false,false,false><<<gg(NCH_*CK_, BB, NU_), 256>>>(hrnn, HH, (long)BB*HH, Wkc, (long)HH*NCH_*CK_, nullptr,
                                                              kc, NCH_*CK_, (long)BB*NCH_*CK_, BB, NCH_*CK_, HH);
    gemm_k<false,false,false><<<gg(NCH_*CV_, BB, NU_), 256>>>(hrnn, HH, (long)BB*HH, Wvc, (long)HH*NCH_*CV_, nullptr,
                                                              vc, NCH_*CV_, (long)BB*NCH_*CV_, BB, NCH_*CV_, HH);
    // 11) attention
    attn_kernel<<<BB, 256>>>();
    // 12) ctx2 = ctx[u] @ Woc[u]   (N=600, K=400)
    gemm_k<false,false,false><<<gg(HH, BB, NU_), 256>>>(ctx, NCH_*CV_, (long)BB*NCH_*CV_, Woc, (long)(NCH_*CV_)*HH, nullptr,
                                                        ctx2, HH, (long)BB*HH, BB, HH, NCH_*CV_);
    // 13) residual + LN + mask blend -> out
    final_kernel<<<NU_*BB, 256>>>(hs, cs, ln_g, ln_b, out);
}

// round 3
// speedup vs baseline: 1.9117x; 1.9117x over previous
#include <cuda_runtime.h>
#include <math.h>
#include <stdint.h>

// ---------------- problem constants ----------------
#define BB   1024
#define IN_  512
#define HH   600
#define NU_  6
#define KK_  4
#define QK_  64
#define VD_  400
#define NCH_ 4
#define CQ_  32
#define CK_  32
#define CV_  100
#define G4H  (4*HH)          // 2400
#define TOT  ((long)BB*NU_*HH)

// ---------------- scratch (device globals, no allocation) ----------------
__device__ float g_k0[BB*QK_];
__device__ float g_v0[BB*VD_];
__device__ float g_ql[NU_*BB*QK_];
__device__ float g_inputs[NU_*BB*VD_];
__device__ float g_mask[BB*NU_];
__device__ float g_gates[(long)NU_*BB*G4H];
__device__ float g_cnew[NU_*BB*HH];
__device__ float g_hrnn[NU_*BB*HH];
__device__ float g_qc[NU_*BB*NCH_*CQ_];
__device__ float g_kc[NU_*BB*NCH_*CK_];
__device__ float g_vc[NU_*BB*NCH_*CV_];
__device__ float g_ctx[NU_*BB*NCH_*CV_];
__device__ float g_ctx2[NU_*BB*HH];

// ============================================================
// fp32 SGEMM (kept for the precision-critical score path only)
// ============================================================
#define FBM 64
#define FBN 64
#define FBK 8
#define FTM 4
#define FTN 4

template<bool TRANSB, bool ACCUM, bool BIAS>
__global__ void gemm_f32(const float* __restrict__ A, int lda, long sA,
                         const float* __restrict__ Bw, long sB,
                         const float* __restrict__ bias,
                         float* __restrict__ C, int ldc, long sC,
                         int M, int N, int Kd)
{
    int u = blockIdx.z;
    A  += (long)u * sA;
    Bw += (long)u * sB;
    C  += (long)u * sC;

    __shared__ float As[FBK][FBM];
    __shared__ float Bs[FBK][FBN];

    int tid = threadIdx.x;
    int tr  = tid >> 4;
    int tc  = tid & 15;
    int rowBase = blockIdx.y * FBM;
    int colBase = blockIdx.x * FBN;

    float acc[FTM][FTN] = {};

    for (int k0 = 0; k0 < Kd; k0 += FBK) {
        #pragma unroll
        for (int i = 0; i < 2; i++) {
            int e = tid + i*256;
            int m = e >> 3, kk = e & 7;
            int gm = rowBase + m;
            As[kk][m] = (gm < M && k0+kk < Kd) ? A[(long)gm*lda + k0 + kk] : 0.f;
        }
        #pragma unroll
        for (int i = 0; i < 2; i++) {
            int e = tid + i*256;
            if (!TRANSB) {
                int kk = e >> 6, n = e & 63;
                int gn = colBase + n;
                Bs[kk][n] = (gn < N && k0+kk < Kd) ? Bw[(long)(k0+kk)*N + gn] : 0.f;
            } else {
                int n = e >> 3, kk = e & 7;
                int gn = colBase + n;
                Bs[kk][n] = (gn < N && k0+kk < Kd) ? Bw[(long)gn*Kd + k0 + kk] : 0.f;
            }
        }
        __syncthreads();
        #pragma unroll
        for (int kk = 0; kk < FBK; kk++) {
            float a[FTM], b[FTN];
            #pragma unroll
            for (int i = 0; i < FTM; i++) a[i] = As[kk][tr*FTM+i];
            #pragma unroll
            for (int j = 0; j < FTN; j++) b[j] = Bs[kk][tc*FTN+j];
            #pragma unroll
            for (int i = 0; i < FTM; i++)
                #pragma unroll
                for (int j = 0; j < FTN; j++)
                    acc[i][j] = fmaf(a[i], b[j], acc[i][j]);
        }
        __syncthreads();
    }

    #pragma unroll
    for (int i = 0; i < FTM; i++) {
        int gm = rowBase + tr*FTM + i;
        if (gm >= M) continue;
        #pragma unroll
        for (int j = 0; j < FTN; j++) {
            int gn = colBase + tc*FTN + j;
            if (gn >= N) continue;
            float v = acc[i][j];
            if (BIAS)  v += bias[gn];
            long ci = (long)gm*ldc + gn;
            if (ACCUM) C[ci] += v; else C[ci] = v;
        }
    }
}

// ============================================================
// tf32 tensor-core GEMM (mma.sync m16n8k8), 128x64x32 tiles
// C[M,N] (+)= A[M,K] * B ; requires M % 128 == 0, K % 4 == 0, N % 4 == 0
// ============================================================
#define TBM 128
#define TBN 64
#define TBK 32

__device__ __forceinline__ uint32_t f2tf32(float f) {
    uint32_t u;
    asm("cvt.rna.tf32.f32 %0, %1;" : "=r"(u) : "f"(f));
    return u;
}

template<bool TRANSB, bool ACCUM, bool BIAS>
__global__ void __launch_bounds__(256, 2)
gemm_tf32(const float* __restrict__ A, int lda, long sA,
          const float* __restrict__ Bw, long sB,
          const float* __restrict__ bias,
          float* __restrict__ C, int ldc, long sC,
          int N, int Kd)
{
    int u = blockIdx.z;
    A  += (long)u * sA;
    Bw += (long)u * sB;
    C  += (long)u * sC;

    __shared__ uint32_t As[TBK][TBM+4];   // k-major
    __shared__ uint32_t Bs[TBK][TBN+4];

    int tid  = threadIdx.x;
    int lane = tid & 31;
    int wid  = tid >> 5;
    int wm   = wid & 3;      // 0..3 (M)
    int wn   = wid >> 2;     // 0..1 (N)
    int r    = lane >> 2;    // 0..7
    int c    = lane & 3;     // 0..3

    int rowBase = blockIdx.y * TBM;   // always fully in-range (M=1024)
    int colBase = blockIdx.x * TBN;

    float acc[2][4][4];
    #pragma unroll
    for (int mi = 0; mi < 2; mi++)
        #pragma unroll
        for (int ni = 0; ni < 4; ni++)
            #pragma unroll
            for (int e = 0; e < 4; e++)
                acc[mi][ni][e] = 0.f;

    for (int k0 = 0; k0 < Kd; k0 += TBK) {
        // ---- load A tile: 128x32 = 1024 float4, 4 per thread ----
        #pragma unroll
        for (int i = 0; i < 4; i++) {
            int f  = tid + i*256;
            int m  = f >> 3;              // 0..127
            int kk = (f & 7) * 4;         // 0..28
            int gk = k0 + kk;
            float4 v = make_float4(0.f,0.f,0.f,0.f);
            if (gk < Kd)
                v = *reinterpret_cast<const float4*>(A + (long)(rowBase+m)*lda + gk);
            As[kk+0][m] = f2tf32(v.x);
            As[kk+1][m] = f2tf32(v.y);
            As[kk+2][m] = f2tf32(v.z);
            As[kk+3][m] = f2tf32(v.w);
        }
        // ---- load B tile: 32x64 = 512 float4-equivalents, 2 per thread ----
        #pragma unroll
        for (int i = 0; i < 2; i++) {
            int f = tid + i*256;
            float4 v = make_float4(0.f,0.f,0.f,0.f);
            if (!TRANSB) {
                int kk = f >> 4;            // 0..31
                int n4 = (f & 15) * 4;      // 0..60
                int gk = k0 + kk, gn = colBase + n4;
                if (gk < Kd && gn < N)
                    v = *reinterpret_cast<const float4*>(Bw + (long)gk*N + gn);
                Bs[kk][n4+0] = f2tf32(v.x);
                Bs[kk][n4+1] = f2tf32(v.y);
                Bs[kk][n4+2] = f2tf32(v.z);
                Bs[kk][n4+3] = f2tf32(v.w);
            } else {
                int n  = f >> 3;            // 0..63
                int k4 = (f & 7) * 4;       // 0..28
                int gn = colBase + n, gk = k0 + k4;
                if (gn < N && gk < Kd)
                    v = *reinterpret_cast<const float4*>(Bw + (long)gn*Kd + gk);
                Bs[k4+0][n] = f2tf32(v.x);
                Bs[k4+1][n] = f2tf32(v.y);
                Bs[k4+2][n] = f2tf32(v.z);
                Bs[k4+3][n] = f2tf32(v.w);
            }
        }
        __syncthreads();

        // ---- compute: 4 k8-steps ----
        #pragma unroll
        for (int ks = 0; ks < TBK; ks += 8) {
            uint32_t a[2][4];
            #pragma unroll
            for (int mi = 0; mi < 2; mi++) {
                int m0 = wm*32 + mi*16 + r;
                a[mi][0] = As[ks + c    ][m0    ];
                a[mi][1] = As[ks + c    ][m0 + 8];
                a[mi][2] = As[ks + c + 4][m0    ];
                a[mi][3] = As[ks + c + 4][m0 + 8];
            }
            uint32_t bf[4][2];
            #pragma unroll
            for (int ni = 0; ni < 4; ni++) {
                int n0 = wn*32 + ni*8 + r;
                bf[ni][0] = Bs[ks + c    ][n0];
                bf[ni][1] = Bs[ks + c + 4][n0];
            }
            #pragma unroll
            for (int mi = 0; mi < 2; mi++)
                #pragma unroll
                for (int ni = 0; ni < 4; ni++) {
                    asm volatile(
                        "mma.sync.aligned.m16n8k8.row.col.f32.tf32.tf32.f32 "
                        "{%0,%1,%2,%3}, {%4,%5,%6,%7}, {%8,%9}, {%0,%1,%2,%3};"
                        : "+f"(acc[mi][ni][0]), "+f"(acc[mi][ni][1]),
                          "+f"(acc[mi][ni][2]), "+f"(acc[mi][ni][3])
                        : "r"(a[mi][0]), "r"(a[mi][1]), "r"(a[mi][2]), "r"(a[mi][3]),
                          "r"(bf[ni][0]), "r"(bf[ni][1]));
                }
        }
        __syncthreads();
    }

    // ---- epilogue ----
    #pragma unroll
    for (int mi = 0; mi < 2; mi++) {
        #pragma unroll
        for (int ni = 0; ni < 4; ni++) {
            int gm = rowBase + wm*32 + mi*16 + r;
            int gn = colBase + wn*32 + ni*8 + c*2;
            #pragma unroll
            for (int e = 0; e < 4; e++) {
                int m = gm + ((e >= 2) ? 8 : 0);
                int n = gn + (e & 1);
                if (n >= N) continue;
                float v = acc[mi][ni][e];
                if (BIAS)  v += bias[n];
                long ci = (long)m*ldc + n;
                if (ACCUM) C[ci] += v; else C[ci] = v;
            }
        }
    }
}

// ---------------- scores / topk / softmax / inputs ----------------
__global__ void scores_kernel(const float* __restrict__ bk,   // [QK]
                              const float* __restrict__ bv)   // [VD]
{
    int b = blockIdx.x;
    int tid = threadIdx.x;   // 256
    __shared__ float s_sc[NU_][2];
    __shared__ float s_p[NU_][2];
    __shared__ float s_m[NU_];

    if (tid < NU_*2) {
        int u = tid >> 1, t = tid & 1;
        const float* q  = g_ql + ((long)u*BB + b)*QK_;
        const float* kv = (t == 0) ? (g_k0 + (long)b*QK_) : bk;
        float s = 0.f;
        #pragma unroll 8
        for (int i = 0; i < QK_; i++) s += q[i]*kv[i];
        s_sc[u][t] = s * 0.125f;   // 1/sqrt(64)
    }
    __syncthreads();
    if (tid == 0) {
        for (int u = 0; u < NU_; u++) {
            int cnt = 0;
            float cu = s_sc[u][0];
            for (int v = 0; v < NU_; v++) {
                float av = s_sc[v][0];
                if (av > cu || (av == cu && v < u)) cnt++;
            }
            float m = (cnt < KK_) ? 1.f : 0.f;
            s_m[u] = m;
            g_mask[(long)b*NU_ + u] = m;
        }
    }
    if (tid < NU_) {
        int u = tid;
        float s0 = s_sc[u][0], s1 = s_sc[u][1];
        float mx = fmaxf(s0, s1);
        float e0 = expf(s0-mx), e1 = expf(s1-mx);
        float inv = 1.f/(e0+e1);
        s_p[u][0] = e0*inv; s_p[u][1] = e1*inv;
    }
    __syncthreads();
    for (int v = tid; v < VD_; v += blockDim.x) {
        float v0v = g_v0[(long)b*VD_ + v];
        float bvv = bv[v];
        #pragma unroll
        for (int u = 0; u < NU_; u++) {
            g_inputs[((long)u*BB + b)*VD_ + v] = s_m[u]*(s_p[u][0]*v0v + s_p[u][1]*bvv);
        }
    }
}

// ---------------- LSTM elementwise ----------------
__global__ void lstm_kernel(const float* __restrict__ bih,    // [NU][4H]
                            const float* __restrict__ bhh,    // [NU][4H]
                            const float* __restrict__ cs)     // [B][NU][H]
{
    long idx = (long)blockIdx.x*blockDim.x + threadIdx.x;
    if (idx >= (long)NU_*BB*HH) return;
    int h  = idx % HH;
    long bu = idx / HH;
    int b  = bu % BB;
    int u  = bu / BB;
    const float* g  = g_gates + ((long)u*BB + b)*G4H;
    const float* bi = bih + (long)u*G4H;
    const float* bh = bhh + (long)u*G4H;
    float ig = g[h]        + bi[h]        + bh[h];
    float fg = g[HH+h]     + bi[HH+h]     + bh[HH+h];
    float gg = g[2*HH+h]   + bi[2*HH+h]   + bh[2*HH+h];
    float og = g[3*HH+h]   + bi[3*HH+h]   + bh[3*HH+h];
    float si = 1.f/(1.f+expf(-ig));
    float sf = 1.f/(1.f+expf(-fg));
    float so = 1.f/(1.f+expf(-og));
    float tg = tanhf(gg);
    float c  = cs[((long)b*NU_ + u)*HH + h];
    float cn = sf*c + si*tg;
    g_cnew[idx] = cn;
    g_hrnn[idx] = so*tanhf(cn);
}

// ---------------- per-batch mini attention ----------------
__global__ void attn_kernel()
{
    int b = blockIdx.x;
    int tid = threadIdx.x;   // 256
    __shared__ float s_q[NU_][NCH_*CQ_];
    __shared__ float s_k[NU_][NCH_*CK_];
    __shared__ float s_v[NU_][NCH_*CV_];
    __shared__ float s_att[NCH_][NU_][NU_];
    __shared__ float s_m[NU_];

    if (tid < NU_) s_m[tid] = g_mask[(long)b*NU_ + tid];
    for (int i = tid; i < NU_*NCH_*CQ_; i += 256) {
        int u = i / (NCH_*CQ_), o = i % (NCH_*CQ_);
        s_q[u][o] = g_qc[((long)u*BB + b)*(NCH_*CQ_) + o];
        s_k[u][o] = g_kc[((long)u*BB + b)*(NCH_*CK_) + o];
    }
    for (int i = tid; i < NU_*NCH_*CV_; i += 256) {
        int u = i / (NCH_*CV_), o = i % (NCH_*CV_);
        s_v[u][o] = g_vc[((long)u*BB + b)*(NCH_*CV_) + o];
    }
    __syncthreads();
    if (tid < NCH_*NU_*NU_) {
        int ch = tid / (NU_*NU_);
        int r  = tid % (NU_*NU_);
        int u = r / NU_, t = r % NU_;
        float s = 0.f;
        #pragma unroll
        for (int q = 0; q < CQ_; q++) s += s_q[u][ch*CQ_+q]*s_k[t][ch*CK_+q];
        s_att[ch][u][t] = s * 0.17677669529663688f;  // 1/sqrt(32)
    }
    __syncthreads();
    if (tid < NCH_*NU_) {
        int ch = tid / NU_, u = tid % NU_;
        float mx = -1e30f;
        #pragma unroll
        for (int t = 0; t < NU_; t++) mx = fmaxf(mx, s_att[ch][u][t]);
        float e[NU_]; float sum = 0.f;
        #pragma unroll
        for (int t = 0; t < NU_; t++) { e[t] = expf(s_att[ch][u][t]-mx); sum += e[t]; }
        float inv = s_m[u]/sum;
        #pragma unroll
        for (int t = 0; t < NU_; t++) s_att[ch][u][t] = e[t]*inv;
    }
    __syncthreads();
    for (int i = tid; i < NU_*NCH_*CV_; i += 256) {
        int u = i / (NCH_*CV_), o = i % (NCH_*CV_);
        int ch = o / CV_, cv = o % CV_;
        float s = 0.f;
        #pragma unroll
        for (int t = 0; t < NU_; t++) s += s_att[ch][u][t]*s_v[t][ch*CV_+cv];
        g_ctx[((long)u*BB + b)*(NCH_*CV_) + o] = s;
    }
}

// ---------------- residual + LayerNorm + blend ----------------
__global__ void final_kernel(const float* __restrict__ hs,    // [B][NU][H]
                             const float* __restrict__ cs,    // [B][NU][H]
                             const float* __restrict__ ln_g,
                             const float* __restrict__ ln_b,
                             float* __restrict__ out)
{
    int blk = blockIdx.x;           // u*B + b
    int u = blk / BB, b = blk % BB;
    int tid = threadIdx.x;          // 256
    int lane = tid & 31, wid = tid >> 5;
    __shared__ float sv[HH];
    __shared__ float wsum[8], wsq[8];

    const float* c2 = g_ctx2 + (long)blk*HH;
    const float* hr = g_hrnn + (long)blk*HH;
    float lsum = 0.f, lsq = 0.f;
    for (int h = tid; h < HH; h += 256) {
        float v = c2[h] + hr[h];
        sv[h] = v; lsum += v; lsq += v*v;
    }
    #pragma unroll
    for (int o = 16; o > 0; o >>= 1) {
        lsum += __shfl_down_sync(0xffffffffu, lsum, o);
        lsq  += __shfl_down_sync(0xffffffffu, lsq, o);
    }
    if (lane == 0) { wsum[wid] = lsum; wsq[wid] = lsq; }
    __syncthreads();
    if (tid == 0) {
        float s = 0.f, q = 0.f;
        #pragma unroll
        for (int w = 0; w < 8; w++) { s += wsum[w]; q += wsq[w]; }
        wsum[0] = s; wsq[0] = q;
    }
    __syncthreads();
    float mu  = wsum[0] * (1.f/HH);
    float var = wsq[0] * (1.f/HH) - mu*mu;
    float inv = rsqrtf(var + 1e-5f);
    float m   = g_mask[(long)b*NU_ + u];
    const float* cn = g_cnew + (long)blk*HH;
    for (int h = tid; h < HH; h += 256) {
        float hn = (sv[h]-mu)*inv*ln_g[h] + ln_b[h];
        long oi = ((long)b*NU_ + u)*HH + h;
        out[oi]       = m*hn    + (1.f-m)*hs[oi];
        out[TOT + oi] = m*cn[h] + (1.f-m)*cs[oi];
    }
}

// ---------------- launch ----------------
static inline dim3 gf(int N, int M, int Z) { return dim3((N+FBN-1)/FBN, (M+FBM-1)/FBM, Z); }
static inline dim3 gt(int N, int Z)        { return dim3((N+TBN-1)/TBN, BB/TBM, Z); }

extern "C" void kernel_launch(void* const* d_in, const int* in_sizes, int n_in,
                              void* d_out, int out_size)
{
    const float* x    = (const float*)d_in[0];
    const float* hs   = (const float*)d_in[1];
    const float* cs   = (const float*)d_in[2];
    const float* Wk   = (const float*)d_in[3];
    const float* bk   = (const float*)d_in[4];
    const float* Wv   = (const float*)d_in[5];
    const float* bv   = (const float*)d_in[6];
    const float* Wq   = (const float*)d_in[7];
    const float* Wqc  = (const float*)d_in[8];
    const float* Wkc  = (const float*)d_in[9];
    const float* Wvc  = (const float*)d_in[10];
    const float* Woc  = (const float*)d_in[11];
    const float* Wih  = (const float*)d_in[12];
    const float* Whh  = (const float*)d_in[13];
    const float* bih  = (const float*)d_in[14];
    const float* bhh  = (const float*)d_in[15];
    const float* ln_g = (const float*)d_in[16];
    const float* ln_b = (const float*)d_in[17];
    float* out = (float*)d_out;

    float *k0, *v0, *ql, *inp, *gates, *hrnn, *qc, *kc, *vc, *ctx, *ctx2;
    cudaGetSymbolAddress((void**)&k0,   g_k0);
    cudaGetSymbolAddress((void**)&v0,   g_v0);
    cudaGetSymbolAddress((void**)&ql,   g_ql);
    cudaGetSymbolAddress((void**)&inp,  g_inputs);
    cudaGetSymbolAddress((void**)&gates,g_gates);
    cudaGetSymbolAddress((void**)&hrnn, g_hrnn);
    cudaGetSymbolAddress((void**)&qc,   g_qc);
    cudaGetSymbolAddress((void**)&kc,   g_kc);
    cudaGetSymbolAddress((void**)&vc,   g_vc);
    cudaGetSymbolAddress((void**)&ctx,  g_ctx);
    cudaGetSymbolAddress((void**)&ctx2, g_ctx2);

    // --- precision-critical score path in exact fp32 (feeds top-k) ---
    // 1) k0 = x @ Wk + bk    (N=64, K=512)
    gemm_f32<false,false,true><<<gf(QK_, BB, 1), 256>>>(x, IN_, 0, Wk, 0, bk, k0, QK_, 0, BB, QK_, IN_);
    // 3) ql[u] = hs_u @ Wq[u]   (N=64, K=600)
    gemm_f32<false,false,false><<<gf(QK_, BB, NU_), 256>>>(hs, NU_*HH, HH, Wq, (long)HH*QK_, nullptr,
                                                           ql, QK_, (long)BB*QK_, BB, QK_, HH);
    // --- everything else on tf32 tensor cores ---
    // 2) v0 = x @ Wv + bv    (N=400, K=512)
    gemm_tf32<false,false,true><<<gt(VD_, 1), 256>>>(x, IN_, 0, Wv, 0, bv, v0, VD_, 0, VD_, IN_);
    // 4) scores / topk / softmax / inputs
    scores_kernel<<<BB, 256>>>(bk, bv);
    // 5) gates = inputs[u] @ Wih[u]^T   (N=2400, K=400)
    gemm_tf32<true,false,false><<<gt(G4H, NU_), 256>>>(inp, VD_, (long)BB*VD_, Wih, (long)G4H*VD_, nullptr,
                                                       gates, G4H, (long)BB*G4H, G4H, VD_);
    // 6) gates += hs_u @ Whh[u]^T       (N=2400, K=600)
    gemm_tf32<true,true,false><<<gt(G4H, NU_), 256>>>(hs, NU_*HH, HH, Whh, (long)G4H*HH, nullptr,
                                                      gates, G4H, (long)BB*G4H, G4H, HH);
    // 7) LSTM
    {
        long tot = (long)NU_*BB*HH;
        lstm_kernel<<<(int)((tot+255)/256), 256>>>(bih, bhh, cs);
    }
    // 8..10) qc/kc/vc projections from h_rnn
    gemm_tf32<false,false,false><<<gt(NCH_*CQ_, NU_), 256>>>(hrnn, HH, (long)BB*HH, Wqc, (long)HH*NCH_*CQ_, nullptr,
                                                             qc, NCH_*CQ_, (long)BB*NCH_*CQ_, NCH_*CQ_, HH);
    gemm_tf32<false,false,false><<<gt(NCH_*CK_, NU_), 256>>>(hrnn, HH, (long)BB*HH, Wkc, (long)HH*NCH_*CK_, nullptr,
                                                             kc, NCH_*CK_, (long)BB*NCH_*CK_, NCH_*CK_, HH);
    gemm_tf32<false,false,false><<<gt(NCH_*CV_, NU_), 256>>>(hrnn, HH, (long)BB*HH, Wvc, (long)HH*NCH_*CV_, nullptr,
                                                             vc, NCH_*CV_, (long)BB*NCH_*CV_, NCH_*CV_, HH);
    // 11) attention
    attn_kernel<<<BB, 256>>>();
    // 12) ctx2 = ctx[u] @ Woc[u]   (N=600, K=400)
    gemm_tf32<false,false,false><<<gt(HH, NU_), 256>>>(ctx, NCH_*CV_, (long)BB*NCH_*CV_, Woc, (long)(NCH_*CV_)*HH, nullptr,
                                                       ctx2, HH, (long)BB*HH, HH, NCH_*CV_);
    // 13) residual + LN + mask blend -> out
    final_kernel<<<NU_*BB, 256>>>(hs, cs, ln_g, ln_b, out);
}

// round 5
// speedup vs baseline: 2.2333x; 1.1683x over previous
#include <cuda_runtime.h>
#include <math.h>
#include <stdint.h>

// ---------------- problem constants ----------------
#define BB   1024
#define IN_  512
#define HH   600
#define NU_  6
#define KK_  4
#define QK_  64
#define VD_  400
#define NCH_ 4
#define CQ_  32
#define CK_  32
#define CV_  100
#define G4H  (4*HH)          // 2400
#define TOT  ((long)BB*NU_*HH)

// ---------------- scratch (device globals, no allocation) ----------------
__device__ float g_k0[BB*QK_];
__device__ float g_v0[BB*VD_];
__device__ float g_ql[NU_*BB*QK_];
__device__ float g_inputs[NU_*BB*VD_];
__device__ float g_mask[BB*NU_];
__device__ float g_gates[(long)NU_*BB*G4H];
__device__ float g_cnew[NU_*BB*HH];
__device__ float g_hrnn[NU_*BB*HH];
__device__ float g_qc[NU_*BB*NCH_*CQ_];
__device__ float g_kc[NU_*BB*NCH_*CK_];
__device__ float g_vc[NU_*BB*NCH_*CV_];
__device__ float g_ctx[NU_*BB*NCH_*CV_];
__device__ float g_ctx2[NU_*BB*HH];

// ============================================================
// fp32 SGEMM (precision-critical score path only)
// ============================================================
#define FBM 64
#define FBN 64
#define FBK 8
#define FTM 4
#define FTN 4

template<bool TRANSB, bool ACCUM, bool BIAS>
__global__ void gemm_f32(const float* __restrict__ A, int lda, long sA,
                         const float* __restrict__ Bw, long sB,
                         const float* __restrict__ bias,
                         float* __restrict__ C, int ldc, long sC,
                         int M, int N, int Kd)
{
    int u = blockIdx.z;
    A  += (long)u * sA;
    Bw += (long)u * sB;
    C  += (long)u * sC;

    __shared__ float As[FBK][FBM];
    __shared__ float Bs[FBK][FBN];

    int tid = threadIdx.x;
    int tr  = tid >> 4;
    int tc  = tid & 15;
    int rowBase = blockIdx.y * FBM;
    int colBase = blockIdx.x * FBN;

    float acc[FTM][FTN] = {};

    for (int k0 = 0; k0 < Kd; k0 += FBK) {
        #pragma unroll
        for (int i = 0; i < 2; i++) {
            int e = tid + i*256;
            int m = e >> 3, kk = e & 7;
            int gm = rowBase + m;
            As[kk][m] = (gm < M && k0+kk < Kd) ? A[(long)gm*lda + k0 + kk] : 0.f;
        }
        #pragma unroll
        for (int i = 0; i < 2; i++) {
            int e = tid + i*256;
            if (!TRANSB) {
                int kk = e >> 6, n = e & 63;
                int gn = colBase + n;
                Bs[kk][n] = (gn < N && k0+kk < Kd) ? Bw[(long)(k0+kk)*N + gn] : 0.f;
            } else {
                int n = e >> 3, kk = e & 7;
                int gn = colBase + n;
                Bs[kk][n] = (gn < N && k0+kk < Kd) ? Bw[(long)gn*Kd + k0 + kk] : 0.f;
            }
        }
        __syncthreads();
        #pragma unroll
        for (int kk = 0; kk < FBK; kk++) {
            float a[FTM], b[FTN];
            #pragma unroll
            for (int i = 0; i < FTM; i++) a[i] = As[kk][tr*FTM+i];
            #pragma unroll
            for (int j = 0; j < FTN; j++) b[j] = Bs[kk][tc*FTN+j];
            #pragma unroll
            for (int i = 0; i < FTM; i++)
                #pragma unroll
                for (int j = 0; j < FTN; j++)
                    acc[i][j] = fmaf(a[i], b[j], acc[i][j]);
        }
        __syncthreads();
    }

    #pragma unroll
    for (int i = 0; i < FTM; i++) {
        int gm = rowBase + tr*FTM + i;
        if (gm >= M) continue;
        #pragma unroll
        for (int j = 0; j < FTN; j++) {
            int gn = colBase + tc*FTN + j;
            if (gn >= N) continue;
            float v = acc[i][j];
            if (BIAS)  v += bias[gn];
            long ci = (long)gm*ldc + gn;
            if (ACCUM) C[ci] += v; else C[ci] = v;
        }
    }
}

// ============================================================
// tf32 tensor-core GEMM, 128x64x16 tiles, double-buffered +
// register-staged pipeline, conflict-free smem (pad 8).
// M must be a multiple of 128 (M = 1024 everywhere here).
// ============================================================
#define TBM 128
#define TBN 64
#define TBK 16

__device__ __forceinline__ uint32_t f2tf32(float f) {
    uint32_t u;
    asm("cvt.rna.tf32.f32 %0, %1;" : "=r"(u) : "f"(f));
    return u;
}

struct TileRegs { float4 a0, a1, b; };

template<bool TRANSB>
__device__ __forceinline__ void load_tile(const float* __restrict__ A, int lda,
                                          const float* __restrict__ Bw,
                                          int N, int Kd, int rowBase, int colBase,
                                          int k0, int tid, TileRegs& t)
{
    const float4 z = make_float4(0.f,0.f,0.f,0.f);
    {
        int m = tid >> 2, kk = (tid & 3) * 4;
        int gk = k0 + kk;
        t.a0 = (gk < Kd) ? *reinterpret_cast<const float4*>(A + (long)(rowBase+m)*lda + gk) : z;
        int f = tid + 256;
        m = f >> 2; kk = (f & 3) * 4; gk = k0 + kk;
        t.a1 = (gk < Kd) ? *reinterpret_cast<const float4*>(A + (long)(rowBase+m)*lda + gk) : z;
    }
    if (!TRANSB) {
        int kk = tid >> 4, n4 = (tid & 15) * 4;
        int gk = k0 + kk, gn = colBase + n4;
        t.b = (gk < Kd && gn < N) ? *reinterpret_cast<const float4*>(Bw + (long)gk*N + gn) : z;
    } else {
        int n = tid >> 2, k4 = (tid & 3) * 4;
        int gn = colBase + n, gk = k0 + k4;
        t.b = (gn < N && gk < Kd) ? *reinterpret_cast<const float4*>(Bw + (long)gn*Kd + gk) : z;
    }
}

template<bool TRANSB>
__device__ __forceinline__ void store_tile(uint32_t As[TBK][TBM+8], uint32_t Bs[TBK][TBN+8],
                                           int tid, const TileRegs& t)
{
    {
        int m = tid >> 2, kk = (tid & 3) * 4;
        As[kk+0][m] = f2tf32(t.a0.x);
        As[kk+1][m] = f2tf32(t.a0.y);
        As[kk+2][m] = f2tf32(t.a0.z);
        As[kk+3][m] = f2tf32(t.a0.w);
        int f = tid + 256;
        m = f >> 2; kk = (f & 3) * 4;
        As[kk+0][m] = f2tf32(t.a1.x);
        As[kk+1][m] = f2tf32(t.a1.y);
        As[kk+2][m] = f2tf32(t.a1.z);
        As[kk+3][m] = f2tf32(t.a1.w);
    }
    if (!TRANSB) {
        int kk = tid >> 4, n4 = (tid & 15) * 4;
        Bs[kk][n4+0] = f2tf32(t.b.x);
        Bs[kk][n4+1] = f2tf32(t.b.y);
        Bs[kk][n4+2] = f2tf32(t.b.z);
        Bs[kk][n4+3] = f2tf32(t.b.w);
    } else {
        int n = tid >> 2, k4 = (tid & 3) * 4;
        Bs[k4+0][n] = f2tf32(t.b.x);
        Bs[k4+1][n] = f2tf32(t.b.y);
        Bs[k4+2][n] = f2tf32(t.b.z);
        Bs[k4+3][n] = f2tf32(t.b.w);
    }
}

__device__ __forceinline__ void compute_tile(const uint32_t As[TBK][TBM+8],
                                             const uint32_t Bs[TBK][TBN+8],
                                             int wm, int wn, int r, int c,
                                             float acc[2][4][4])
{
    #pragma unroll
    for (int ks = 0; ks < TBK; ks += 8) {
        uint32_t a[2][4];
        #pragma unroll
        for (int mi = 0; mi < 2; mi++) {
            int m0 = wm*32 + mi*16 + r;
            a[mi][0] = As[ks + c    ][m0    ];
            a[mi][1] = As[ks + c    ][m0 + 8];
            a[mi][2] = As[ks + c + 4][m0    ];
            a[mi][3] = As[ks + c + 4][m0 + 8];
        }
        uint32_t b[4][2];
        #pragma unroll
        for (int ni = 0; ni < 4; ni++) {
            int n0 = wn*32 + ni*8 + r;
            b[ni][0] = Bs[ks + c    ][n0];
            b[ni][1] = Bs[ks + c + 4][n0];
        }
        #pragma unroll
        for (int mi = 0; mi < 2; mi++)
            #pragma unroll
            for (int ni = 0; ni < 4; ni++) {
                asm volatile(
                    "mma.sync.aligned.m16n8k8.row.col.f32.tf32.tf32.f32 "
                    "{%0,%1,%2,%3}, {%4,%5,%6,%7}, {%8,%9}, {%0,%1,%2,%3};"
                    : "+f"(acc[mi][ni][0]), "+f"(acc[mi][ni][1]),
                      "+f"(acc[mi][ni][2]), "+f"(acc[mi][ni][3])
                    : "r"(a[mi][0]), "r"(a[mi][1]), "r"(a[mi][2]), "r"(a[mi][3]),
                      "r"(b[ni][0]), "r"(b[ni][1]));
            }
    }
}

template<bool TRANSB>
__device__ __forceinline__ void gemm_seg(const float* __restrict__ A, int lda,
                                         const float* __restrict__ Bw,
                                         int N, int Kd, int rowBase, int colBase,
                                         int tid, int wm, int wn, int r, int c,
                                         uint32_t As[2][TBK][TBM+8],
                                         uint32_t Bs[2][TBK][TBN+8],
                                         float acc[2][4][4])
{
    TileRegs t;
    load_tile<TRANSB>(A, lda, Bw, N, Kd, rowBase, colBase, 0, tid, t);
    store_tile<TRANSB>(As[0], Bs[0], tid, t);
    __syncthreads();
    int nk = (Kd + TBK - 1) / TBK;
    for (int kt = 0; kt < nk; kt++) {
        int st = kt & 1;
        bool more = (kt + 1 < nk);
        if (more) load_tile<TRANSB>(A, lda, Bw, N, Kd, rowBase, colBase, (kt+1)*TBK, tid, t);
        compute_tile(As[st], Bs[st], wm, wn, r, c, acc);
        __syncthreads();
        if (more) {
            store_tile<TRANSB>(As[st^1], Bs[st^1], tid, t);
            __syncthreads();
        }
    }
}

__device__ __forceinline__ void epilogue(float* __restrict__ C, int ldc,
                                         const float* __restrict__ bias, bool useBias,
                                         int N, int rowBase, int colBase,
                                         int wm, int wn, int r, int c,
                                         const float acc[2][4][4])
{
    #pragma unroll
    for (int mi = 0; mi < 2; mi++) {
        #pragma unroll
        for (int ni = 0; ni < 4; ni++) {
            int gm = rowBase + wm*32 + mi*16 + r;
            int gn = colBase + wn*32 + ni*8 + c*2;
            #pragma unroll
            for (int e = 0; e < 4; e++) {
                int m = gm + ((e >= 2) ? 8 : 0);
                int n = gn + (e & 1);
                if (n >= N) continue;
                float v = acc[mi][ni][e];
                if (useBias) v += bias[n];
                C[(long)m*ldc + n] = v;
            }
        }
    }
}

// ---- generic single-segment tf32 GEMM ----
template<bool TRANSB, bool BIAS>
__global__ void __launch_bounds__(256)
gemm_tc(const float* __restrict__ A, int lda, long sA,
        const float* __restrict__ Bw, long sB,
        const float* __restrict__ bias,
        float* __restrict__ C, int ldc, long sC,
        int N, int Kd)
{
    int u = blockIdx.z;
    A  += (long)u * sA;
    Bw += (long)u * sB;
    C  += (long)u * sC;

    __shared__ uint32_t As[2][TBK][TBM+8];
    __shared__ uint32_t Bs[2][TBK][TBN+8];

    int tid  = threadIdx.x;
    int lane = tid & 31, wid = tid >> 5;
    int wm = wid & 3, wn = wid >> 2;
    int r = lane >> 2, c = lane & 3;
    int rowBase = blockIdx.y * TBM;
    int colBase = blockIdx.x * TBN;

    float acc[2][4][4];
    #pragma unroll
    for (int mi = 0; mi < 2; mi++)
        #pragma unroll
        for (int ni = 0; ni < 4; ni++)
            #pragma unroll
            for (int e = 0; e < 4; e++) acc[mi][ni][e] = 0.f;

    gemm_seg<TRANSB>(A, lda, Bw, N, Kd, rowBase, colBase, tid, wm, wn, r, c, As, Bs, acc);
    epilogue(C, ldc, bias, BIAS, N, rowBase, colBase, wm, wn, r, c, acc);
}

// ---- fused gates GEMM: gates = inputs@Wih^T + hs@Whh^T ----
__global__ void __launch_bounds__(256)
gates_tc(const float* __restrict__ Wih, const float* __restrict__ Whh,
         const float* __restrict__ hs, float* __restrict__ gates)
{
    int u = blockIdx.z;
    const float* A0 = g_inputs + (long)u*BB*VD_;
    const float* B0 = Wih + (long)u*G4H*VD_;
    const float* A1 = hs + (long)u*HH;
    const float* B1 = Whh + (long)u*G4H*HH;
    float* C = gates + (long)u*BB*G4H;

    __shared__ uint32_t As[2][TBK][TBM+8];
    __shared__ uint32_t Bs[2][TBK][TBN+8];

    int tid  = threadIdx.x;
    int lane = tid & 31, wid = tid >> 5;
    int wm = wid & 3, wn = wid >> 2;
    int r = lane >> 2, c = lane & 3;
    int rowBase = blockIdx.y * TBM;
    int colBase = blockIdx.x * TBN;

    float acc[2][4][4];
    #pragma unroll
    for (int mi = 0; mi < 2; mi++)
        #pragma unroll
        for (int ni = 0; ni < 4; ni++)
            #pragma unroll
            for (int e = 0; e < 4; e++) acc[mi][ni][e] = 0.f;

    gemm_seg<true>(A0, VD_,     B0, G4H, VD_, rowBase, colBase, tid, wm, wn, r, c, As, Bs, acc);
    gemm_seg<true>(A1, NU_*HH,  B1, G4H, HH,  rowBase, colBase, tid, wm, wn, r, c, As, Bs, acc);
    epilogue(C, G4H, nullptr, false, G4H, rowBase, colBase, wm, wn, r, c, acc);
}

// ---------------- scores / topk / softmax / inputs ----------------
__global__ void scores_kernel(const float* __restrict__ bk,   // [QK]
                              const float* __restrict__ bv)   // [VD]
{
    int b = blockIdx.x;
    int tid = threadIdx.x;   // 256
    __shared__ float s_sc[NU_][2];
    __shared__ float s_p[NU_][2];
    __shared__ float s_m[NU_];

    if (tid < NU_*2) {
        int u = tid >> 1, t = tid & 1;
        const float* q  = g_ql + ((long)u*BB + b)*QK_;
        const float* kv = (t == 0) ? (g_k0 + (long)b*QK_) : bk;
        float s = 0.f;
        #pragma unroll 8
        for (int i = 0; i < QK_; i++) s += q[i]*kv[i];
        s_sc[u][t] = s * 0.125f;   // 1/sqrt(64)
    }
    __syncthreads();
    if (tid == 0) {
        for (int u = 0; u < NU_; u++) {
            int cnt = 0;
            float cu = s_sc[u][0];
            for (int v = 0; v < NU_; v++) {
                float av = s_sc[v][0];
                if (av > cu || (av == cu && v < u)) cnt++;
            }
            float m = (cnt < KK_) ? 1.f : 0.f;
            s_m[u] = m;
            g_mask[(long)b*NU_ + u] = m;
        }
    }
    if (tid < NU_) {
        int u = tid;
        float s0 = s_sc[u][0], s1 = s_sc[u][1];
        float mx = fmaxf(s0, s1);
        float e0 = expf(s0-mx), e1 = expf(s1-mx);
        float inv = 1.f/(e0+e1);
        s_p[u][0] = e0*inv; s_p[u][1] = e1*inv;
    }
    __syncthreads();
    for (int v = tid; v < VD_; v += blockDim.x) {
        float v0v = g_v0[(long)b*VD_ + v];
        float bvv = bv[v];
        #pragma unroll
        for (int u = 0; u < NU_; u++) {
            g_inputs[((long)u*BB + b)*VD_ + v] = s_m[u]*(s_p[u][0]*v0v + s_p[u][1]*bvv);
        }
    }
}

// ---------------- LSTM elementwise ----------------
__global__ void lstm_kernel(const float* __restrict__ bih,    // [NU][4H]
                            const float* __restrict__ bhh,    // [NU][4H]
                            const float* __restrict__ cs)     // [B][NU][H]
{
    long idx = (long)blockIdx.x*blockDim.x + threadIdx.x;
    if (idx >= (long)NU_*BB*HH) return;
    int h  = idx % HH;
    long bu = idx / HH;
    int b  = bu % BB;
    int u  = bu / BB;
    const float* g  = g_gates + ((long)u*BB + b)*G4H;
    const float* bi = bih + (long)u*G4H;
    const float* bh = bhh + (long)u*G4H;
    float ig = g[h]        + bi[h]        + bh[h];
    float fg = g[HH+h]     + bi[HH+h]     + bh[HH+h];
    float gg = g[2*HH+h]   + bi[2*HH+h]   + bh[2*HH+h];
    float og = g[3*HH+h]   + bi[3*HH+h]   + bh[3*HH+h];
    float si = 1.f/(1.f+expf(-ig));
    float sf = 1.f/(1.f+expf(-fg));
    float so = 1.f/(1.f+expf(-og));
    float tg = tanhf(gg);
    float c  = cs[((long)b*NU_ + u)*HH + h];
    float cn = sf*c + si*tg;
    g_cnew[idx] = cn;
    g_hrnn[idx] = so*tanhf(cn);
}

// ---------------- per-batch mini attention ----------------
__global__ void attn_kernel()
{
    int b = blockIdx.x;
    int tid = threadIdx.x;   // 256
    __shared__ float s_q[NU_][NCH_*CQ_];
    __shared__ float s_k[NU_][NCH_*CK_];
    __shared__ float s_v[NU_][NCH_*CV_];
    __shared__ float s_att[NCH_][NU_][NU_];
    __shared__ float s_m[NU_];

    if (tid < NU_) s_m[tid] = g_mask[(long)b*NU_ + tid];
    for (int i = tid; i < NU_*NCH_*CQ_; i += 256) {
        int u = i / (NCH_*CQ_), o = i % (NCH_*CQ_);
        s_q[u][o] = g_qc[((long)u*BB + b)*(NCH_*CQ_) + o];
        s_k[u][o] = g_kc[((long)u*BB + b)*(NCH_*CK_) + o];
    }
    for (int i = tid; i < NU_*NCH_*CV_; i += 256) {
        int u = i / (NCH_*CV_), o = i % (NCH_*CV_);
        s_v[u][o] = g_vc[((long)u*BB + b)*(NCH_*CV_) + o];
    }
    __syncthreads();
    if (tid < NCH_*NU_*NU_) {
        int ch = tid / (NU_*NU_);
        int r  = tid % (NU_*NU_);
        int u = r / NU_, t = r % NU_;
        float s = 0.f;
        #pragma unroll
        for (int q = 0; q < CQ_; q++) s += s_q[u][ch*CQ_+q]*s_k[t][ch*CK_+q];
        s_att[ch][u][t] = s * 0.17677669529663688f;  // 1/sqrt(32)
    }
    __syncthreads();
    if (tid < NCH_*NU_) {
        int ch = tid / NU_, u = tid % NU_;
        float mx = -1e30f;
        #pragma unroll
        for (int t = 0; t < NU_; t++) mx = fmaxf(mx, s_att[ch][u][t]);
        float e[NU_]; float sum = 0.f;
        #pragma unroll
        for (int t = 0; t < NU_; t++) { e[t] = expf(s_att[ch][u][t]-mx); sum += e[t]; }
        float inv = s_m[u]/sum;
        #pragma unroll
        for (int t = 0; t < NU_; t++) s_att[ch][u][t] = e[t]*inv;
    }
    __syncthreads();
    for (int i = tid; i < NU_*NCH_*CV_; i += 256) {
        int u = i / (NCH_*CV_), o = i % (NCH_*CV_);
        int ch = o / CV_, cv = o % CV_;
        float s = 0.f;
        #pragma unroll
        for (int t = 0; t < NU_; t++) s += s_att[ch][u][t]*s_v[t][ch*CV_+cv];
        g_ctx[((long)u*BB + b)*(NCH_*CV_) + o] = s;
    }
}

// ---------------- residual + LayerNorm + blend ----------------
__global__ void final_kernel(const float* __restrict__ hs,    // [B][NU][H]
                             const float* __restrict__ cs,    // [B][NU][H]
                             const float* __restrict__ ln_g,
                             const float* __restrict__ ln_b,
                             float* __restrict__ out)
{
    int blk = blockIdx.x;           // u*B + b
    int u = blk / BB, b = blk % BB;
    int tid = threadIdx.x;          // 256
    int lane = tid & 31, wid = tid >> 5;
    __shared__ float sv[HH];
    __shared__ float wsum[8], wsq[8];

    const float* c2 = g_ctx2 + (long)blk*HH;
    const float* hr = g_hrnn + (long)blk*HH;
    float lsum = 0.f, lsq = 0.f;
    for (int h = tid; h < HH; h += 256) {
        float v = c2[h] + hr[h];
        sv[h] = v; lsum += v; lsq += v*v;
    }
    #pragma unroll
    for (int o = 16; o > 0; o >>= 1) {
        lsum += __shfl_down_sync(0xffffffffu, lsum, o);
        lsq  += __shfl_down_sync(0xffffffffu, lsq, o);
    }
    if (lane == 0) { wsum[wid] = lsum; wsq[wid] = lsq; }
    __syncthreads();
    if (tid == 0) {
        float s = 0.f, q = 0.f;
        #pragma unroll
        for (int w = 0; w < 8; w++) { s += wsum[w]; q += wsq[w]; }
        wsum[0] = s; wsq[0] = q;
    }
    __syncthreads();
    float mu  = wsum[0] * (1.f/HH);
    float var = wsq[0] * (1.f/HH) - mu*mu;
    float inv = rsqrtf(var + 1e-5f);
    float m   = g_mask[(long)b*NU_ + u];
    const float* cn = g_cnew + (long)blk*HH;
    for (int h = tid; h < HH; h += 256) {
        float hn = (sv[h]-mu)*inv*ln_g[h] + ln_b[h];
        long oi = ((long)b*NU_ + u)*HH + h;
        out[oi]       = m*hn    + (1.f-m)*hs[oi];
        out[TOT + oi] = m*cn[h] + (1.f-m)*cs[oi];
    }
}

// ---------------- launch ----------------
static inline dim3 gf(int N, int M, int Z) { return dim3((N+FBN-1)/FBN, (M+FBM-1)/FBM, Z); }
static inline dim3 gt(int N, int Z)        { return dim3((N+TBN-1)/TBN, BB/TBM, Z); }

extern "C" void kernel_launch(void* const* d_in, const int* in_sizes, int n_in,
                              void* d_out, int out_size)
{
    const float* x    = (const float*)d_in[0];
    const float* hs   = (const float*)d_in[1];
    const float* cs   = (const float*)d_in[2];
    const float* Wk   = (const float*)d_in[3];
    const float* bk   = (const float*)d_in[4];
    const float* Wv   = (const float*)d_in[5];
    const float* bv   = (const float*)d_in[6];
    const float* Wq   = (const float*)d_in[7];
    const float* Wqc  = (const float*)d_in[8];
    const float* Wkc  = (const float*)d_in[9];
    const float* Wvc  = (const float*)d_in[10];
    const float* Woc  = (const float*)d_in[11];
    const float* Wih  = (const float*)d_in[12];
    const float* Whh  = (const float*)d_in[13];
    const float* bih  = (const float*)d_in[14];
    const float* bhh  = (const float*)d_in[15];
    const float* ln_g = (const float*)d_in[16];
    const float* ln_b = (const float*)d_in[17];
    float* out = (float*)d_out;

    float *k0, *v0, *ql, *gates, *hrnn, *qc, *kc, *vc, *ctx, *ctx2;
    cudaGetSymbolAddress((void**)&k0,   g_k0);
    cudaGetSymbolAddress((void**)&v0,   g_v0);
    cudaGetSymbolAddress((void**)&ql,   g_ql);
    cudaGetSymbolAddress((void**)&gates,g_gates);
    cudaGetSymbolAddress((void**)&hrnn, g_hrnn);
    cudaGetSymbolAddress((void**)&qc,   g_qc);
    cudaGetSymbolAddress((void**)&kc,   g_kc);
    cudaGetSymbolAddress((void**)&vc,   g_vc);
    cudaGetSymbolAddress((void**)&ctx,  g_ctx);
    cudaGetSymbolAddress((void**)&ctx2, g_ctx2);

    // --- precision-critical score path in exact fp32 (feeds top-k) ---
    gemm_f32<false,false,true><<<gf(QK_, BB, 1), 256>>>(x, IN_, 0, Wk, 0, bk, k0, QK_, 0, BB, QK_, IN_);
    gemm_f32<false,false,false><<<gf(QK_, BB, NU_), 256>>>(hs, NU_*HH, HH, Wq, (long)HH*QK_, nullptr,
                                                           ql, QK_, (long)BB*QK_, BB, QK_, HH);
    // --- tf32 tensor cores for everything downstream of the mask ---
    // v0 = x @ Wv + bv    (N=400, K=512)
    gemm_tc<false,true><<<gt(VD_, 1), 256>>>(x, IN_, 0, Wv, 0, bv, v0, VD_, 0, VD_, IN_);
    // scores / topk / softmax / inputs
    scores_kernel<<<BB, 256>>>(bk, bv);
    // gates = inputs@Wih^T + hs@Whh^T  (fused, N=2400, K=400+600)
    gates_tc<<<gt(G4H, NU_), 256>>>(Wih, Whh, hs, gates);
    // LSTM
    {
        long tot = (long)NU_*BB*HH;
        lstm_kernel<<<(int)((tot+255)/256), 256>>>(bih, bhh, cs);
    }
    // qc/kc/vc projections from h_rnn
    gemm_tc<false,false><<<gt(NCH_*CQ_, NU_), 256>>>(hrnn, HH, (long)BB*HH, Wqc, (long)HH*NCH_*CQ_, nullptr,
                                                     qc, NCH_*CQ_, (long)BB*NCH_*CQ_, NCH_*CQ_, HH);
    gemm_tc<false,false><<<gt(NCH_*CK_, NU_), 256>>>(hrnn, HH, (long)BB*HH, Wkc, (long)HH*NCH_*CK_, nullptr,
                                                     kc, NCH_*CK_, (long)BB*NCH_*CK_, NCH_*CK_, HH);
    gemm_tc<false,false><<<gt(NCH_*CV_, NU_), 256>>>(hrnn, HH, (long)BB*HH, Wvc, (long)HH*NCH_*CV_, nullptr,
                                                     vc, NCH_*CV_, (long)BB*NCH_*CV_, NCH_*CV_, HH);
    // attention
    attn_kernel<<<BB, 256>>>();
    // ctx2 = ctx[u] @ Woc[u]   (N=600, K=400)
    gemm_tc<false,false><<<gt(HH, NU_), 256>>>(ctx, NCH_*CV_, (long)BB*NCH_*CV_, Woc, (long)(NCH_*CV_)*HH, nullptr,
                                               ctx2, HH, (long)BB*HH, HH, NCH_*CV_);
    // residual + LN + mask blend -> out
    final_kernel<<<NU_*BB, 256>>>(hs, cs, ln_g, ln_b, out);
}